// round 3
// baseline (speedup 1.0000x reference)
#include <cuda_runtime.h>
#include <cuda_bf16.h>

// RelativePositionEncoding (AF3-style), GB300 sm_103a — R3
//
// out[i,j,:] = W_pos[dr] + W_tok[dt] + same_ent*w_ent + W_chain[dk]
// Fused:  (pos,tok) -> one 132-row table F;  (chain,ent) -> 12-row table C.
//   rows [0,66):   F[r] = W_pos[r]  + W_tok[65]   (indexed by dr when !scr)
//   rows [66,132): F[t] = W_pos[32] + W_tok[t]    (indexed by dt when  scr)
//   C[e*6+k] = W_chain[k] + e*w_ent
//
// R3 changes vs R2 (179.8us, DRAM 79.3%):
//  - Kernel A precomputes packed (f,dc) for ALL 1536^2 pairs into a 4.7MB
//    uint16 scratch (L2-resident) and resets the work counter (graph-safe).
//  - Kernel B: 444 persistent CTAs (3/SM, all resident). Table built once
//    per CTA. Warps steal 32-j units via a global atomic counter with a
//    one-unit prefetch to hide atomic latency. Kills wave quantization
//    (3.46 waves -> 1 persistent wave, ~2.5% end skew).

#define N_TOK 1536
#define CZ 128
#define JB 32
#define UNITS_PER_ROW (N_TOK / JB)          // 48
#define N_UNITS (N_TOK * UNITS_PER_ROW)      // 73728
#define TBL_FLOATS (144 * CZ)
#define SMEM_BYTES (TBL_FLOATS * 4)          // 73728 B
#define N_CTAS 444                            // 148 SMs * 3

__device__ unsigned short g_sidx[(size_t)N_TOK * N_TOK];  // packed f | dc<<8
__device__ int g_ctr;

// ---------------- Kernel A: pair-index precompute + counter reset ----------
__global__ __launch_bounds__(256)
void build_idx(const int* __restrict__ asym,
               const int* __restrict__ resi,
               const int* __restrict__ enti,
               const int* __restrict__ toki,
               const int* __restrict__ symi)
{
    const int i = blockIdx.x;
    if (i == 0 && threadIdx.x == 0) g_ctr = 0;

    const int ai = asym[i], ri = resi[i], ei = enti[i], ti = toki[i], si = symi[i];
    unsigned short* row = g_sidx + (size_t)i * N_TOK;

    for (int j = threadIdx.x; j < N_TOK; j += 256) {
        const int aj = __ldg(asym + j);
        const int rj = __ldg(resi + j);
        const int ej = __ldg(enti + j);
        const int tj = __ldg(toki + j);
        const int sj = __ldg(symi + j);

        const bool sc  = (ai == aj);
        const bool scr = sc && (ri == rj);
        int f;
        if (scr)      f = 66 + min(max(ti - tj + 32, 0), 64);
        else if (sc)  f = min(max(ri - rj + 32, 0), 64);
        else          f = 65;
        const bool se = (ei == ej);
        const int  dk = se ? min(max(si - sj + 2, 0), 4) : 5;
        const int  dc = (se ? 6 : 0) + dk;
        row[j] = (unsigned short)(f | (dc << 8));
    }
}

// ---------------- Kernel B: persistent store engine ------------------------
__global__ __launch_bounds__(256, 3)
void relpos_kernel(const float* __restrict__ W, float* __restrict__ out)
{
    extern __shared__ float sW[];   // [144][128]
    const int tid = threadIdx.x;

    // Fused pos/tok table (132 rows).
    // W rows: [0,66)=pos, [66,132)=tok, 132=w_ent, [133,139)=chain
    #pragma unroll 4
    for (int idx = tid; idx < 132 * CZ; idx += 256) {
        const int row = idx >> 7;
        const int c   = idx & (CZ - 1);
        float v;
        if (row < 66) v = W[row * CZ + c] + W[131 * CZ + c];
        else          v = W[32  * CZ + c] + W[row * CZ + c];
        sW[idx] = v;
    }
    // Fused chain/entity table (12 rows at offset 132).
    for (int idx = tid; idx < 12 * CZ; idx += 256) {
        const int row = idx >> 7;
        const int c   = idx & (CZ - 1);
        const int e   = row / 6;
        const int k   = row % 6;
        float v = W[(133 + k) * CZ + c];
        if (e) v += W[132 * CZ + c];
        sW[132 * CZ + idx] = v;
    }
    __syncthreads();

    const int lane = tid & 31;
    const float4* __restrict__ t4 = reinterpret_cast<const float4*>(sW);
    const float4* __restrict__ c4 = t4 + 132 * 32;
    float4* __restrict__ out4 = reinterpret_cast<float4*>(out);

    // Warp-granular work stealing with one-unit prefetch.
    int u;
    if (lane == 0) u = atomicAdd(&g_ctr, 1);
    u = __shfl_sync(0xFFFFFFFFu, u, 0);

    while (u < N_UNITS) {
        int nu;
        if (lane == 0) nu = atomicAdd(&g_ctr, 1);   // prefetch next unit
        nu = __shfl_sync(0xFFFFFFFFu, nu, 0);

        const int i  = u / UNITS_PER_ROW;
        const int jb = (u - i * UNITS_PER_ROW) * JB;

        // 64B coalesced load of 32 packed indices for this unit.
        const int myp = (int)g_sidx[(size_t)i * N_TOK + jb + lane];

        float4* __restrict__ o = out4 + ((size_t)i * N_TOK + jb) * 32 + lane;

        #pragma unroll 4
        for (int k = 0; k < JB; k++) {
            const unsigned p = (unsigned)__shfl_sync(0xFFFFFFFFu, myp, k);
            const float4 a = t4[(p & 0xFFu) * 32 + lane];
            const float4 c = c4[(p >> 8)    * 32 + lane];
            float4 r;
            r.x = a.x + c.x; r.y = a.y + c.y; r.z = a.z + c.z; r.w = a.w + c.w;
            __stcs(&o[(size_t)k * 32], r);
        }
        u = nu;
    }
}

extern "C" void kernel_launch(void* const* d_in, const int* in_sizes, int n_in,
                              void* d_out, int out_size)
{
    const int*   asym = (const int*)d_in[0];
    const int*   resi = (const int*)d_in[1];
    const int*   enti = (const int*)d_in[2];
    const int*   toki = (const int*)d_in[3];
    const int*   symi = (const int*)d_in[4];
    const float* W    = (const float*)d_in[5];
    float*       out  = (float*)d_out;

    cudaFuncSetAttribute(relpos_kernel,
                         cudaFuncAttributeMaxDynamicSharedMemorySize, SMEM_BYTES);

    build_idx<<<N_TOK, 256>>>(asym, resi, enti, toki, symi);
    relpos_kernel<<<N_CTAS, 256, SMEM_BYTES>>>(W, out);
}

// round 4
// speedup vs baseline: 1.4411x; 1.4411x over previous
#include <cuda_runtime.h>
#include <cuda_bf16.h>

// RelativePositionEncoding (AF3-style), GB300 sm_103a — R4
//
// out[i,j,:] = W_pos[dr] + W_tok[dt] + same_ent*w_ent + W_chain[dk]
// Fusions (proven R2):
//   F[0..66)  = W_pos[r]  + W_tok[65]   (indexed by d_residue when !same_cr)
//   F[66..132)= W_pos[32] + W_tok[t]    (indexed by d_token  when  same_cr)
//   C[e*6+k]  = W_chain[k] + e*w_ent
//
// R4 = R2 hot loop + persistent CTAs with STATIC interleaved unit assignment.
//   456 CTAs (3/SM x 152 SM), unit = 192 consecutive j's of one row i.
//   12288 units -> 26.95/CTA, ceil 27 -> 0.2% end skew (vs R2's 3.46-wave
//   ~13% tail idle). No atomics, no shfl, no index scratch in gmem.

#define N_TOK 1536
#define CZ 128
#define QJ 192                          // j's per work unit
#define UNITS_PER_ROW (N_TOK / QJ)      // 8
#define N_UNITS (N_TOK * UNITS_PER_ROW) // 12288
#define N_CTAS 456                      // 152 SMs * 3 resident CTAs
#define TBL_FLOATS (144 * CZ)
#define SMEM_BYTES (TBL_FLOATS * 4 + QJ * 2)

__global__ __launch_bounds__(256, 3)
void relpos_kernel(const int* __restrict__ asym,
                   const int* __restrict__ resi,
                   const int* __restrict__ enti,
                   const int* __restrict__ toki,
                   const int* __restrict__ symi,
                   const float* __restrict__ W,
                   float* __restrict__ out)
{
    extern __shared__ float sW[];                              // [144][128]
    unsigned short* sIdx = (unsigned short*)(sW + TBL_FLOATS); // [QJ]

    const int tid = threadIdx.x;

    // ---- One-time table build (per CTA) ----
    // W rows: [0,66)=pos, [66,132)=tok, 132=w_ent, [133,139)=chain
    #pragma unroll 4
    for (int idx = tid; idx < 132 * CZ; idx += 256) {
        const int row = idx >> 7;
        const int c   = idx & (CZ - 1);
        float v;
        if (row < 66) v = W[row * CZ + c] + W[131 * CZ + c];   // pos[row]+tok[65]
        else          v = W[32  * CZ + c] + W[row * CZ + c];   // pos[32]+tok[row-66]
        sW[idx] = v;
    }
    for (int idx = tid; idx < 12 * CZ; idx += 256) {
        const int row = idx >> 7;
        const int c   = idx & (CZ - 1);
        const int e   = row / 6;
        const int k   = row % 6;
        float v = W[(133 + k) * CZ + c];
        if (e) v += W[132 * CZ + c];
        sW[132 * CZ + idx] = v;
    }

    const int lane = tid & 31;
    const int warp = tid >> 5;
    const float4* __restrict__ t4 = reinterpret_cast<const float4*>(sW);
    const float4* __restrict__ c4 = t4 + 132 * 32;
    float4* __restrict__ out4 = reinterpret_cast<float4*>(out);

    // ---- Persistent loop over statically-assigned units ----
    for (int u = blockIdx.x; u < N_UNITS; u += N_CTAS) {
        const int i  = u >> 3;               // u / UNITS_PER_ROW
        const int jb = (u & 7) * QJ;

        const int ai = __ldg(asym + i);
        const int ri = __ldg(resi + i);
        const int ei = __ldg(enti + i);
        const int ti = __ldg(toki + i);
        const int si = __ldg(symi + i);

        __syncthreads();   // WAR: prior unit's hot loop done before sIdx overwrite
        if (tid < QJ) {
            const int j  = jb + tid;
            const int aj = __ldg(asym + j);
            const int rj = __ldg(resi + j);
            const int ej = __ldg(enti + j);
            const int tj = __ldg(toki + j);
            const int sj = __ldg(symi + j);

            const bool sc  = (ai == aj);
            const bool scr = sc && (ri == rj);
            int f;
            if (scr)      f = 66 + min(max(ti - tj + 32, 0), 64);
            else if (sc)  f = min(max(ri - rj + 32, 0), 64);
            else          f = 65;
            const bool se = (ei == ej);
            const int  dk = se ? min(max(si - sj + 2, 0), 4) : 5;
            const int  dc = (se ? 6 : 0) + dk;
            sIdx[tid] = (unsigned short)(f | (dc << 8));
        }
        __syncthreads();   // RAW: sIdx visible to all warps

        float4* __restrict__ o = out4 + ((size_t)i * N_TOK + jb) * 32 + lane;

        #pragma unroll 2
        for (int j = warp * 2; j < QJ; j += 16) {
            const unsigned p0 = sIdx[j];
            const unsigned p1 = sIdx[j + 1];

            const float4 a0 = t4[(p0 & 0xFFu) * 32 + lane];
            const float4 b0 = c4[(p0 >> 8)    * 32 + lane];
            const float4 a1 = t4[(p1 & 0xFFu) * 32 + lane];
            const float4 b1 = c4[(p1 >> 8)    * 32 + lane];

            float4 r0, r1;
            r0.x = a0.x + b0.x; r0.y = a0.y + b0.y; r0.z = a0.z + b0.z; r0.w = a0.w + b0.w;
            r1.x = a1.x + b1.x; r1.y = a1.y + b1.y; r1.z = a1.z + b1.z; r1.w = a1.w + b1.w;

            __stcs(&o[(size_t)j * 32],       r0);
            __stcs(&o[(size_t)(j + 1) * 32], r1);
        }
    }
}

extern "C" void kernel_launch(void* const* d_in, const int* in_sizes, int n_in,
                              void* d_out, int out_size)
{
    const int*   asym = (const int*)d_in[0];
    const int*   resi = (const int*)d_in[1];
    const int*   enti = (const int*)d_in[2];
    const int*   toki = (const int*)d_in[3];
    const int*   symi = (const int*)d_in[4];
    const float* W    = (const float*)d_in[5];
    float*       out  = (float*)d_out;

    cudaFuncSetAttribute(relpos_kernel,
                         cudaFuncAttributeMaxDynamicSharedMemorySize, SMEM_BYTES);

    relpos_kernel<<<N_CTAS, 256, SMEM_BYTES>>>(asym, resi, enti, toki, symi, W, out);
}

// round 5
// speedup vs baseline: 1.5698x; 1.0893x over previous
#include <cuda_runtime.h>
#include <cuda_bf16.h>

// RelativePositionEncoding (AF3-style), GB300 sm_103a — R5
//
// out[i,j,:] = W_pos[dr] + W_tok[dt] + same_ent*w_ent + W_chain[dk]
// Fusions (proven R2):
//   F[0..66)  = W_pos[r]  + W_tok[65]   (indexed by d_residue when !same_cr)
//   F[66..132)= W_pos[32] + W_tok[t]    (indexed by d_token  when  same_cr)
//   C[e*6+k]  = W_chain[k] + e*w_ent
//
// R5 = R2 structure (1536 blocks, one row i per block, sIdx staged in smem,
// 2xLDS.128 + 4 FADD + STG.128-streaming hot loop) with 512-thread blocks:
//   3 CTAs/SM x 512 thr = 48 warps/SM (2x R2's 24) -> double store MLP.
//   16 warps share one table build (halves chip-wide prologue work).
//   __launch_bounds__(512,3) caps regs at 42 to fit the regfile.

#define N_TOK 1536
#define CZ 128
#define TBL_FLOATS (144 * CZ)                  // 73728 B table
#define IDX_OFF    TBL_FLOATS
#define SMEM_BYTES (TBL_FLOATS * 4 + N_TOK * 2)

__global__ __launch_bounds__(512, 3)
void relpos_kernel(const int* __restrict__ asym,
                   const int* __restrict__ resi,
                   const int* __restrict__ enti,
                   const int* __restrict__ toki,
                   const int* __restrict__ symi,
                   const float* __restrict__ W,
                   float* __restrict__ out)
{
    extern __shared__ float sW[];                            // [144][128]
    unsigned short* sIdx = (unsigned short*)(sW + IDX_OFF);  // [1536]

    const int tid = threadIdx.x;
    const int i   = blockIdx.x;

    // ---- Phase 1a: fused pos/tok table (132 rows) ----
    // W rows: [0,66)=pos, [66,132)=tok, 132=w_ent, [133,139)=chain
    #pragma unroll 4
    for (int idx = tid; idx < 132 * CZ; idx += 512) {
        const int row = idx >> 7;
        const int c   = idx & (CZ - 1);
        float v;
        if (row < 66) v = W[row * CZ + c] + W[131 * CZ + c];   // pos[row]+tok[65]
        else          v = W[32  * CZ + c] + W[row * CZ + c];   // pos[32]+tok[row-66]
        sW[idx] = v;
    }
    // ---- Phase 1b: fused chain/entity table (12 rows at offset 132) ----
    for (int idx = tid; idx < 12 * CZ; idx += 512) {
        const int row = idx >> 7;
        const int c   = idx & (CZ - 1);
        const int e   = row / 6;
        const int k   = row % 6;
        float v = W[(133 + k) * CZ + c];
        if (e) v += W[132 * CZ + c];
        sW[132 * CZ + idx] = v;
    }

    // ---- Phase 1c: per-j packed indices for this i ----
    const int ai = asym[i], ri = resi[i], ei = enti[i], ti = toki[i], si = symi[i];
    for (int j = tid; j < N_TOK; j += 512) {
        const int aj = __ldg(asym + j);
        const int rj = __ldg(resi + j);
        const int ej = __ldg(enti + j);
        const int tj = __ldg(toki + j);
        const int sj = __ldg(symi + j);

        const bool sc  = (ai == aj);
        const bool scr = sc && (ri == rj);
        int f;
        if (scr)      f = 66 + min(max(ti - tj + 32, 0), 64);
        else if (sc)  f = min(max(ri - rj + 32, 0), 64);
        else          f = 65;
        const bool se = (ei == ej);
        const int  dk = se ? min(max(si - sj + 2, 0), 4) : 5;
        const int  dc = (se ? 6 : 0) + dk;
        sIdx[j] = (unsigned short)(f | (dc << 8));
    }
    __syncthreads();

    // ---- Phase 2: hot loop — 16 warps stride j, unroll x2 ----
    const int lane = tid & 31;
    const int warp = tid >> 5;

    const float4* __restrict__ t4 = reinterpret_cast<const float4*>(sW);  // row stride 32
    const float4* __restrict__ c4 = t4 + 132 * 32;
    float4* __restrict__ out4 = reinterpret_cast<float4*>(out) + (size_t)i * N_TOK * 32;

    #pragma unroll 2
    for (int j = warp * 2; j < N_TOK; j += 32) {
        const unsigned p0 = sIdx[j];
        const unsigned p1 = sIdx[j + 1];

        const float4 a0 = t4[(p0 & 0xFFu) * 32 + lane];
        const float4 b0 = c4[(p0 >> 8)    * 32 + lane];
        const float4 a1 = t4[(p1 & 0xFFu) * 32 + lane];
        const float4 b1 = c4[(p1 >> 8)    * 32 + lane];

        float4 r0, r1;
        r0.x = a0.x + b0.x; r0.y = a0.y + b0.y; r0.z = a0.z + b0.z; r0.w = a0.w + b0.w;
        r1.x = a1.x + b1.x; r1.y = a1.y + b1.y; r1.z = a1.z + b1.z; r1.w = a1.w + b1.w;

        __stcs(&out4[(size_t)j * 32 + lane],       r0);
        __stcs(&out4[(size_t)(j + 1) * 32 + lane], r1);
    }
}

extern "C" void kernel_launch(void* const* d_in, const int* in_sizes, int n_in,
                              void* d_out, int out_size)
{
    const int*   asym = (const int*)d_in[0];
    const int*   resi = (const int*)d_in[1];
    const int*   enti = (const int*)d_in[2];
    const int*   toki = (const int*)d_in[3];
    const int*   symi = (const int*)d_in[4];
    const float* W    = (const float*)d_in[5];
    float*       out  = (float*)d_out;

    cudaFuncSetAttribute(relpos_kernel,
                         cudaFuncAttributeMaxDynamicSharedMemorySize, SMEM_BYTES);

    relpos_kernel<<<N_TOK, 512, SMEM_BYTES>>>(asym, resi, enti, toki, symi, W, out);
}